// round 1
// baseline (speedup 1.0000x reference)
#include <cuda_runtime.h>
#include <math.h>

#define T_LEN 2048
#define NTHREADS 256
#define PER_THREAD 8   // T_LEN / NTHREADS

__global__ __launch_bounds__(NTHREADS)
void scpp_kernel(const float* __restrict__ event_times,
                 const float* __restrict__ input_mask,
                 const float* __restrict__ t0p,
                 const float* __restrict__ t1p,
                 const float* __restrict__ mup,
                 const float* __restrict__ betap,
                 float* __restrict__ out)
{
    const int row = blockIdx.x;
    const int tid = threadIdx.x;

    // scalars (broadcast loads, L2-hit)
    const float mu   = log1pf(expf(mup[0]));
    const float beta = log1pf(expf(betap[0]));
    const float t0   = t0p[0];
    const float t1   = t1p[0];

    // ---- vectorized loads: each thread owns 8 contiguous elements ----
    const size_t rbase = (size_t)row * T_LEN;
    const float4* etv = reinterpret_cast<const float4*>(event_times + rbase) + tid * 2;
    const float4* mkv = reinterpret_cast<const float4*>(input_mask  + rbase) + tid * 2;
    float4 e0 = etv[0], e1 = etv[1];
    float4 m0 = mkv[0], m1 = mkv[1];

    float tv[PER_THREAD] = {e0.x, e0.y, e0.z, e0.w, e1.x, e1.y, e1.z, e1.w};
    float mv[PER_THREAD] = {m0.x, m0.y, m0.z, m0.w, m1.x, m1.y, m1.z, m1.w};

    // ---- local pass: loglik partial, masked count, last masked time ----
    const int base = tid * PER_THREAD;
    float ll = 0.0f;
    int   m  = 0;
    float last_t = 0.0f;
    int   has = 0;
    #pragma unroll
    for (int j = 0; j < PER_THREAD; j++) {
        if (mv[j] > 0.5f) {
            ll = ll + (fmaf(mu, tv[j], -beta * (float)(base + j)));
            m++;
            last_t = tv[j];
            has = 1;
        }
    }

    // ---- block scans: inclusive count scan + inclusive forward-fill of last_t
    __shared__ int   sC[NTHREADS];
    __shared__ float sL[NTHREADS];
    __shared__ int   sH[NTHREADS];
    sC[tid] = m; sL[tid] = last_t; sH[tid] = has;
    __syncthreads();
    #pragma unroll
    for (int off = 1; off < NTHREADS; off <<= 1) {
        int   c = sC[tid];
        float l = sL[tid];
        int   h = sH[tid];
        if (tid >= off) {
            c += sC[tid - off];
            if (!h) { l = sL[tid - off]; h = sH[tid - off]; }
        }
        __syncthreads();
        sC[tid] = c; sL[tid] = l; sH[tid] = h;
        __syncthreads();
    }

    const int   Kincl = sC[tid];
    const int   Kexcl = Kincl - m;
    float prev_t = t0;
    if (tid > 0 && sH[tid - 1]) prev_t = sL[tid - 1];
    const int   Mtot     = sC[NTHREADS - 1];
    const float lastT_all = sH[NTHREADS - 1] ? sL[NTHREADS - 1] : t0;
    __syncthreads();

    // ---- compensator contribution (exp work gated by underflow bound) ----
    float contrib = 0.0f;
    const float bK = beta * (float)Kexcl;
    if (m > 0 && bK < 104.0f) {   // expf underflows to exactly 0 beyond ~-103.97
        const float scale = expf(-bK);
        const float emb   = expf(-beta);
        float c = 1.0f;                       // e^{-beta * local_rank}
        float prevE = expf(mu * prev_t);
        float A = 0.0f;
        #pragma unroll
        for (int j = 0; j < PER_THREAD; j++) {
            if (mv[j] > 0.5f) {
                float E = expf(mu * tv[j]);
                A = fmaf(c, E - prevE, A);
                prevE = E;
                c *= emb;
            }
        }
        contrib = scale * A;
    }

    // ---- block reductions: sum(ll), sum(contrib) ----
    __shared__ float sR[NTHREADS];
    __shared__ float sR2[NTHREADS];
    sR[tid]  = ll;
    sR2[tid] = contrib;
    __syncthreads();
    #pragma unroll
    for (int off = NTHREADS / 2; off > 0; off >>= 1) {
        if (tid < off) {
            sR[tid]  += sR[tid + off];
            sR2[tid] += sR2[tid + off];
        }
        __syncthreads();
    }

    if (tid == 0) {
        float comp = sR2[0];
        const float bM = beta * (float)Mtot;
        if (bM < 104.0f) {
            comp += expf(-bM) * (expf(mu * t1) - expf(mu * lastT_all));
        }
        out[row] = sR[0] - comp / mu;
    }
}

extern "C" void kernel_launch(void* const* d_in, const int* in_sizes, int n_in,
                              void* d_out, int out_size)
{
    const float* event_times = (const float*)d_in[0];
    // d_in[1] = spatial_locations : unused by the op
    const float* input_mask  = (const float*)d_in[2];
    const float* t0          = (const float*)d_in[3];
    const float* t1          = (const float*)d_in[4];
    const float* mu_param    = (const float*)d_in[5];
    const float* beta_param  = (const float*)d_in[6];
    float* out = (float*)d_out;

    const int n_rows = out_size;  // 8192
    scpp_kernel<<<n_rows, NTHREADS>>>(event_times, input_mask, t0, t1,
                                      mu_param, beta_param, out);
}

// round 2
// speedup vs baseline: 1.2731x; 1.2731x over previous
#include <cuda_runtime.h>
#include <math.h>

#define T_LEN 2048
#define NTHREADS 256
#define NWARPS 8
#define PER_THREAD 8   // T_LEN / NTHREADS
#define FULL 0xFFFFFFFFu

__global__ __launch_bounds__(NTHREADS)
void scpp_kernel(const float* __restrict__ event_times,
                 const float* __restrict__ input_mask,
                 const float* __restrict__ t0p,
                 const float* __restrict__ t1p,
                 const float* __restrict__ mup,
                 const float* __restrict__ betap,
                 float* __restrict__ out)
{
    const int row  = blockIdx.x;
    const int tid  = threadIdx.x;
    const int lane = tid & 31;
    const int wid  = tid >> 5;

    // scalars (broadcast loads, L2-hit)
    const float mu   = log1pf(expf(__ldg(mup)));
    const float beta = log1pf(expf(__ldg(betap)));
    const float t0   = __ldg(t0p);
    const float t1   = __ldg(t1p);

    // ---- vectorized loads: each thread owns 8 contiguous elements ----
    const size_t rbase = (size_t)row * T_LEN;
    const float4* etv = reinterpret_cast<const float4*>(event_times + rbase) + tid * 2;
    const float4* mkv = reinterpret_cast<const float4*>(input_mask  + rbase) + tid * 2;
    float4 e0 = etv[0], e1 = etv[1];
    float4 m0 = mkv[0], m1 = mkv[1];

    float tv[PER_THREAD] = {e0.x, e0.y, e0.z, e0.w, e1.x, e1.y, e1.z, e1.w};
    float mv[PER_THREAD] = {m0.x, m0.y, m0.z, m0.w, m1.x, m1.y, m1.z, m1.w};

    // ---- local pass: loglik partials, masked count, last masked time ----
    const int base = tid * PER_THREAD;
    float sumt = 0.0f;   // sum mask * t
    float sumi = 0.0f;   // sum mask * index
    int   m    = 0;
    float lfill = 0.0f;  // last masked time in my segment
    int   hfill = 0;     // segment has a masked event
    #pragma unroll
    for (int j = 0; j < PER_THREAD; j++) {
        bool on = mv[j] > 0.5f;
        sumt  = fmaf(mv[j], tv[j], sumt);
        sumi  = fmaf(mv[j], (float)(base + j), sumi);
        m    += on ? 1 : 0;
        lfill = on ? tv[j] : lfill;
        hfill = on ? 1 : hfill;
    }
    float ll = fmaf(mu, sumt, -beta * sumi);

    // ---- warp inclusive scan of (count, fill) via shuffles ----
    int   c = m;
    float l = lfill;
    int   h = hfill;
    #pragma unroll
    for (int off = 1; off < 32; off <<= 1) {
        int   cu = __shfl_up_sync(FULL, c, off);
        float lu = __shfl_up_sync(FULL, l, off);
        int   hu = __shfl_up_sync(FULL, h, off);
        if (lane >= off) {
            c += cu;
            if (!h) { l = lu; h = hu; }
        }
    }

    // ---- warp totals -> smem, warp 0 scans 8 entries ----
    __shared__ int   wC[NWARPS];
    __shared__ float wL[NWARPS];
    __shared__ int   wH[NWARPS];
    __shared__ int   pC[NWARPS];     // exclusive count prefix per warp
    __shared__ float pL[NWARPS];     // exclusive fill per warp
    __shared__ int   pH[NWARPS];
    __shared__ int   sMtot;
    __shared__ float sLastT;

    if (lane == 31) { wC[wid] = c; wL[wid] = l; wH[wid] = h; }
    __syncthreads();

    if (wid == 0 && lane < NWARPS) {
        int   cc = wC[lane];
        float ww = wL[lane];
        int   hh = wH[lane];
        #pragma unroll
        for (int off = 1; off < NWARPS; off <<= 1) {
            int   cu = __shfl_up_sync(0xFF, cc, off);
            float lu = __shfl_up_sync(0xFF, ww, off);
            int   hu = __shfl_up_sync(0xFF, hh, off);
            if (lane >= off) {
                cc += cu;
                if (!hh) { ww = lu; hh = hu; }
            }
        }
        // exclusive versions
        int   ce = __shfl_up_sync(0xFF, cc, 1);
        float le = __shfl_up_sync(0xFF, ww, 1);
        int   he = __shfl_up_sync(0xFF, hh, 1);
        pC[lane] = (lane == 0) ? 0 : ce;
        pL[lane] = (lane == 0) ? 0.0f : le;
        pH[lane] = (lane == 0) ? 0 : he;
        if (lane == NWARPS - 1) {
            sMtot  = cc;
            sLastT = hh ? ww : t0;
        }
    }
    __syncthreads();

    // ---- per-thread exclusive quantities ----
    const int Kexcl = c - m + pC[wid];

    float pl = __shfl_up_sync(FULL, l, 1);
    int   ph = __shfl_up_sync(FULL, h, 1);
    if (lane == 0) { pl = pL[wid]; ph = pH[wid]; }
    const float prev_t = ph ? pl : t0;

    // ---- compensator contribution (exp work gated by underflow bound) ----
    float contrib = 0.0f;
    const float bK = beta * (float)Kexcl;
    if (m > 0 && bK < 104.0f) {   // expf underflows to exactly 0 beyond ~-103.97
        const float scale = expf(-bK);
        const float emb   = expf(-beta);
        float cw = 1.0f;                       // e^{-beta * local_rank}
        float prevE = expf(mu * prev_t);
        float A = 0.0f;
        #pragma unroll
        for (int j = 0; j < PER_THREAD; j++) {
            if (mv[j] > 0.5f) {
                float E = expf(mu * tv[j]);
                A = fmaf(cw, E - prevE, A);
                prevE = E;
                cw *= emb;
            }
        }
        contrib = scale * A;
    }

    // ---- reductions via shuffles ----
    #pragma unroll
    for (int off = 16; off > 0; off >>= 1) {
        ll      += __shfl_down_sync(FULL, ll, off);
        contrib += __shfl_down_sync(FULL, contrib, off);
    }
    __shared__ float rLL[NWARPS];
    __shared__ float rCB[NWARPS];
    if (lane == 0) { rLL[wid] = ll; rCB[wid] = contrib; }
    __syncthreads();

    if (wid == 0 && lane < NWARPS) {
        float a = rLL[lane];
        float b = rCB[lane];
        #pragma unroll
        for (int off = NWARPS / 2; off > 0; off >>= 1) {
            a += __shfl_down_sync(0xFF, a, off);
            b += __shfl_down_sync(0xFF, b, off);
        }
        if (lane == 0) {
            float comp = b;
            const float bM = beta * (float)sMtot;
            if (bM < 104.0f) {
                comp += expf(-bM) * (expf(mu * t1) - expf(mu * sLastT));
            }
            out[row] = a - comp / mu;
        }
    }
}

extern "C" void kernel_launch(void* const* d_in, const int* in_sizes, int n_in,
                              void* d_out, int out_size)
{
    const float* event_times = (const float*)d_in[0];
    // d_in[1] = spatial_locations : unused by the op
    const float* input_mask  = (const float*)d_in[2];
    const float* t0          = (const float*)d_in[3];
    const float* t1          = (const float*)d_in[4];
    const float* mu_param    = (const float*)d_in[5];
    const float* beta_param  = (const float*)d_in[6];
    float* out = (float*)d_out;

    const int n_rows = out_size;  // 8192
    scpp_kernel<<<n_rows, NTHREADS>>>(event_times, input_mask, t0, t1,
                                      mu_param, beta_param, out);
}